// round 13
// baseline (speedup 1.0000x reference)
#include <cuda_runtime.h>
#include <cuda_bf16.h>
#include <math.h>
#include <stdint.h>

#define NFR    2048
#define BATCHB 8
#define AROWS  (NFR*BATCHB)     /* 16384 */
#define NBINS  257
#define STFTN  514
#define NFFT   512
#define HIDD   512
#define TAUD   524544
#define LTXT   512
#define KPAD   272
#define FPOS   200000.0f
#define FNEG   (-100000.0f)

#define FMA2(d,a,b) asm("fma.rn.f32x2 %0, %1, %2, %0;" : "+l"(d) : "l"(a), "l"(b))

/* ---------------- static device scratch ---------------- */
__device__ float  g_table[STFTN*NFFT];
__device__ float  g_frames[(size_t)AROWS*NFFT];
__device__ float  g_stft[(size_t)AROWS*STFTN];
__device__ float  g_feat[(size_t)AROWS*KPAD];
__device__ float  g_fc1p[512*KPAD];
__device__ float  g_prebn[(size_t)AROWS*HIDD];
__device__ double g_bnstat[1024];
__device__ float  g_x0[(size_t)AROWS*HIDD];
__device__ float  g_x1[(size_t)AROWS*HIDD];
__device__ float  g_x2[(size_t)AROWS*HIDD];
__device__ float  g_zbuf[(size_t)2*AROWS*1024];
__device__ float  g_htext[(size_t)BATCHB*LTXT*HIDD];
__device__ float  g_side[(size_t)BATCHB*512*512];
__device__ float  g_scores[(size_t)BATCHB*NFR*LTXT];

static __device__ __forceinline__ float sigf(float x){
    return __fdividef(1.0f, 1.0f + __expf(-x));
}
static __device__ __forceinline__ float tanhfast(float x){
    return 1.0f - __fdividef(2.0f, __expf(2.0f*x) + 1.0f);
}

static __device__ __forceinline__ uint32_t smem_u32(const void* p){
    uint32_t a;
    asm("{ .reg .u64 t; cvta.to.shared.u64 t, %1; cvt.u32.u64 %0, t; }"
        : "=r"(a) : "l"(p));
    return a;
}

static __device__ __forceinline__ uint32_t f2tf(float x){
    uint32_t r; asm("cvt.rna.tf32.f32 %0, %1;" : "=r"(r) : "f"(x)); return r;
}
static __device__ __forceinline__ void mma8(float4& d,
    uint32_t a0,uint32_t a1,uint32_t a2,uint32_t a3,uint32_t b0,uint32_t b1){
    asm("mma.sync.aligned.m16n8k8.row.col.f32.tf32.tf32.f32 "
        "{%0,%1,%2,%3},{%4,%5,%6,%7},{%8,%9},{%0,%1,%2,%3};"
        : "+f"(d.x),"+f"(d.y),"+f"(d.z),"+f"(d.w)
        : "r"(a0),"r"(a1),"r"(a2),"r"(a3),"r"(b0),"r"(b1));
}

/* ---------------- init kernels ---------------- */
__global__ void k_table(){
    int i = blockIdx.x*blockDim.x + threadIdx.x;
    if (i < 1024) g_bnstat[i] = 0.0;    /* BN accumulators */
    if (i >= STFTN*NFFT) return;
    int j = i >> 9, k = i & 511;
    int bin = (j < NBINS) ? j : (j - NBINS);
    int ph = (k*bin) & 511;
    float ang = (float)ph * 0.012271846303085130f;
    g_table[i] = (j < NBINS) ? cosf(ang) : sinf(ang);
}

__global__ void k_frames(const float* __restrict__ x){
    int i = blockIdx.x*blockDim.x + threadIdx.x;
    if (i >= AROWS*NFFT) return;
    int row = i >> 9, n = i & 511;
    int f = row >> 3, b = row & 7;
    float w = 0.5f*(1.0f - cosf((float)n * 0.012271846303085130f));
    g_frames[i] = x[(size_t)b*TAUD + f*256 + n] * w;
}

__global__ void k_magfeat(const float* __restrict__ mean, const float* __restrict__ scale){
    int i = blockIdx.x*blockDim.x + threadIdx.x;
    if (i >= AROWS*KPAD) return;
    int row = i / KPAD, col = i - row*KPAD;
    float v = 0.f;
    if (col < NBINS){
        float re = g_stft[(size_t)row*STFTN + col];
        float im = g_stft[(size_t)row*STFTN + NBINS + col];
        v = (sqrtf(re*re + im*im) + mean[col]) * scale[col];
    }
    g_feat[i] = v;
}

__global__ void k_padw(const float* __restrict__ w){
    int i = blockIdx.x*blockDim.x + threadIdx.x;
    if (i >= 512*KPAD) return;
    int r = i / KPAD, c = i - r*KPAD;
    g_fc1p[i] = (c < NBINS) ? w[r*NBINS + c] : 0.f;
}

/* ---------------- tf32 tensor-core GEMM (unchanged) ---------------- */
__global__ void __launch_bounds__(256) k_gemm(
    const float* __restrict__ A, int lda, long long sA,
    const float* __restrict__ B, int ldb, long long sB,
    float* __restrict__ C, int ldc, long long sC,
    const float* __restrict__ bias, long long sBias,
    int M, int N, int K)
{
    __shared__ uint32_t As[2][128*16];
    __shared__ uint32_t Bs[2][128*16];
    int tid = threadIdx.x;
    int bz = blockIdx.z;
    A += (size_t)bz*sA; B += (size_t)bz*sB; C += (size_t)bz*sC;
    int m0 = blockIdx.y*128, n0 = blockIdx.x*128;

    int wid = tid >> 5, lane = tid & 31;
    int wm = wid & 3, wn = wid >> 2;
    int g = lane >> 2, tg = lane & 3;
    int aoff = ((tg ^ (g & 3)) << 2);

    int lrow = tid >> 2, lkq = tid & 3;

    float4 acc[2][8];
#pragma unroll
    for (int i=0;i<2;i++)
#pragma unroll
        for (int j=0;j<8;j++) acc[i][j] = make_float4(0.f,0.f,0.f,0.f);

    const float4 z4 = make_float4(0.f,0.f,0.f,0.f);
    int mm0 = m0 + lrow, mm1 = m0 + lrow + 64;
    int nn0 = n0 + lrow, nn1 = n0 + lrow + 64;

    float4 pA0, pA1, pB0, pB1;
    pA0 = (mm0 < M) ? *(const float4*)(A + (size_t)mm0*lda + lkq*4) : z4;
    pA1 = (mm1 < M) ? *(const float4*)(A + (size_t)mm1*lda + lkq*4) : z4;
    pB0 = (nn0 < N) ? *(const float4*)(B + (size_t)nn0*ldb + lkq*4) : z4;
    pB1 = (nn1 < N) ? *(const float4*)(B + (size_t)nn1*ldb + lkq*4) : z4;

    int s0 = lrow & 3;
    {
        uint32_t* b0 = As[0] + lrow*16 + lkq;
        b0[((0^s0)<<2)] = f2tf(pA0.x); b0[((1^s0)<<2)] = f2tf(pA0.y);
        b0[((2^s0)<<2)] = f2tf(pA0.z); b0[((3^s0)<<2)] = f2tf(pA0.w);
        uint32_t* b1 = As[0] + (lrow+64)*16 + lkq;
        b1[((0^s0)<<2)] = f2tf(pA1.x); b1[((1^s0)<<2)] = f2tf(pA1.y);
        b1[((2^s0)<<2)] = f2tf(pA1.z); b1[((3^s0)<<2)] = f2tf(pA1.w);
        uint32_t* c0 = Bs[0] + lrow*16 + lkq;
        c0[((0^s0)<<2)] = f2tf(pB0.x); c0[((1^s0)<<2)] = f2tf(pB0.y);
        c0[((2^s0)<<2)] = f2tf(pB0.z); c0[((3^s0)<<2)] = f2tf(pB0.w);
        uint32_t* c1 = Bs[0] + (lrow+64)*16 + lkq;
        c1[((0^s0)<<2)] = f2tf(pB1.x); c1[((1^s0)<<2)] = f2tf(pB1.y);
        c1[((2^s0)<<2)] = f2tf(pB1.z); c1[((3^s0)<<2)] = f2tf(pB1.w);
    }
    __syncthreads();

    int kt = K >> 4;
    for (int kb = 0; kb < kt; kb++){
        int buf = kb & 1;
        bool more = (kb + 1 < kt);
        if (more){
            int ko = (kb+1)*16;
            pA0 = (mm0 < M) ? *(const float4*)(A + (size_t)mm0*lda + ko + lkq*4) : z4;
            pA1 = (mm1 < M) ? *(const float4*)(A + (size_t)mm1*lda + ko + lkq*4) : z4;
            pB0 = (nn0 < N) ? *(const float4*)(B + (size_t)nn0*ldb + ko + lkq*4) : z4;
            pB1 = (nn1 < N) ? *(const float4*)(B + (size_t)nn1*ldb + ko + lkq*4) : z4;
        }

        uint4 aLo[2], aHi[2];
#pragma unroll
        for (int i=0;i<2;i++){
            int r = wm*32 + i*16 + g;
            aLo[i] = *(const uint4*)&As[buf][r*16 + aoff];
            aHi[i] = *(const uint4*)&As[buf][(r+8)*16 + aoff];
        }
#pragma unroll
        for (int j=0;j<8;j++){
            uint4 bv = *(const uint4*)&Bs[buf][(wn*64 + j*8 + g)*16 + aoff];
#pragma unroll
            for (int i=0;i<2;i++){
                mma8(acc[i][j], aLo[i].x, aHi[i].x, aLo[i].y, aHi[i].y, bv.x, bv.y);
                mma8(acc[i][j], aLo[i].z, aHi[i].z, aLo[i].w, aHi[i].w, bv.z, bv.w);
            }
        }

        if (more){
            int nb = buf ^ 1;
            uint32_t* b0 = As[nb] + lrow*16 + lkq;
            b0[((0^s0)<<2)] = f2tf(pA0.x); b0[((1^s0)<<2)] = f2tf(pA0.y);
            b0[((2^s0)<<2)] = f2tf(pA0.z); b0[((3^s0)<<2)] = f2tf(pA0.w);
            uint32_t* b1 = As[nb] + (lrow+64)*16 + lkq;
            b1[((0^s0)<<2)] = f2tf(pA1.x); b1[((1^s0)<<2)] = f2tf(pA1.y);
            b1[((2^s0)<<2)] = f2tf(pA1.z); b1[((3^s0)<<2)] = f2tf(pA1.w);
            uint32_t* c0 = Bs[nb] + lrow*16 + lkq;
            c0[((0^s0)<<2)] = f2tf(pB0.x); c0[((1^s0)<<2)] = f2tf(pB0.y);
            c0[((2^s0)<<2)] = f2tf(pB0.z); c0[((3^s0)<<2)] = f2tf(pB0.w);
            uint32_t* c1 = Bs[nb] + (lrow+64)*16 + lkq;
            c1[((0^s0)<<2)] = f2tf(pB1.x); c1[((1^s0)<<2)] = f2tf(pB1.y);
            c1[((2^s0)<<2)] = f2tf(pB1.z); c1[((3^s0)<<2)] = f2tf(pB1.w);
        }
        __syncthreads();
    }

#pragma unroll
    for (int i=0;i<2;i++){
        int r0 = m0 + wm*32 + i*16 + g;
#pragma unroll
        for (int j=0;j<8;j++){
            int col = n0 + wn*64 + j*8 + tg*2;
            if (col + 2 <= N){
                float bx = bias ? bias[(size_t)bz*sBias + col]     : 0.f;
                float by = bias ? bias[(size_t)bz*sBias + col + 1] : 0.f;
                if (r0 < M)
                    *(float2*)&C[(size_t)r0*ldc + col] =
                        make_float2(acc[i][j].x + bx, acc[i][j].y + by);
                if (r0 + 8 < M)
                    *(float2*)&C[(size_t)(r0+8)*ldc + col] =
                        make_float2(acc[i][j].z + bx, acc[i][j].w + by);
            } else if (col < N){
                float bx = bias ? bias[(size_t)bz*sBias + col] : 0.f;
                if (r0 < M)     C[(size_t)r0*ldc + col]     = acc[i][j].x + bx;
                if (r0 + 8 < M) C[(size_t)(r0+8)*ldc + col] = acc[i][j].z + bx;
            }
        }
    }
}

/* ---------------- BatchNorm (stats zeroed in k_table) ---------------- */
__global__ void k_bnstats(){
    int r0 = blockIdx.x * 128;
    int c = threadIdx.x;
    double s0=0,q0=0,s1=0,q1=0;
    for (int r=0;r<128;r++){
        float v0 = g_prebn[(size_t)(r0+r)*512 + c];
        float v1 = g_prebn[(size_t)(r0+r)*512 + c + 256];
        s0 += v0; q0 += (double)v0*v0;
        s1 += v1; q1 += (double)v1*v1;
    }
    atomicAdd(&g_bnstat[c], s0);       atomicAdd(&g_bnstat[512+c], q0);
    atomicAdd(&g_bnstat[c+256], s1);   atomicAdd(&g_bnstat[512+c+256], q1);
}

__global__ void k_bnapply(const float* __restrict__ gam, const float* __restrict__ bet){
    size_t i = (size_t)blockIdx.x*blockDim.x + threadIdx.x;
    if (i >= (size_t)AROWS*512) return;
    int col = (int)(i & 511);
    double mu = g_bnstat[col] * (1.0/16384.0);
    double var = g_bnstat[512+col] * (1.0/16384.0) - mu*mu;
    float rs = rsqrtf((float)var + 1e-5f);
    float v = g_prebn[i];
    g_x0[i] = tanhf(gam[col]*(v-(float)mu)*rs + bet[col]);
}

/* ---------------- persistent bi-LSTM: DSMEM cluster exchange ----------------
   16 clusters of 8 CTAs = 16 (dir,batch) chains. CTA owns 32 hidden units.
   h exchange via st.shared::cluster (mapa) into every peer's double-buffered
   hbuf + smem mbarrier (64 arrivals: 8 warps x 8 CTAs). Recurrence never
   touches global memory.                                                     */
__global__ void __launch_bounds__(256,1) __cluster_dims__(8,1,1) k_lstm(
    const float* __restrict__ zin,    /* [dir][T*8][1024] or null (text) */
    const float* __restrict__ whh,    /* [dir][1024][256] */
    const float* __restrict__ wihT,   /* text: [dir][1024][44] */
    const float* __restrict__ biasT,  /* text: [dir][1024] */
    const int*   __restrict__ idx,    /* text: [8][T] */
    float* __restrict__ xout,
    int T, int outMode)
{
    int cta   = blockIdx.x;
    int chain = cta >> 3;          /* 0..15 = dir*8 + b */
    int dir   = chain >> 3;
    int b     = chain & 7;
    uint32_t cid;
    asm("mov.u32 %0, %%cluster_ctarank;" : "=r"(cid));
    int tid   = threadIdx.x;
    int w     = tid >> 5;
    int lane  = tid & 31;
    int r = lane >> 1, half = lane & 1;
    int g = r >> 2, u = r & 3;
    int ubase = (int)cid*32 + w*4; /* this warp's 4 units */
    int grow  = g*256 + ubase + u;
    int uu = lane & 3;

    __shared__ __align__(16) float hbuf[2][256];
    __shared__ float xbuf[8][64][4];       /* [warp][step&63][unit] */
    __shared__ __align__(8) unsigned long long mbar;

    float4 rw[32];
    {
        const float4* wsrc = (const float4*)(whh + (size_t)dir*1024*256
                                             + (size_t)grow*256 + half*128);
#pragma unroll
        for (int q=0;q<32;q++) rw[q] = wsrc[q];
    }
    if (tid < 64) ((float4*)hbuf[0])[tid] = make_float4(0.f,0.f,0.f,0.f);
    uint32_t mbar_a = smem_u32(&mbar);
    if (tid == 0){
        asm volatile("mbarrier.init.shared.b64 [%0], %1;"
                     :: "r"(mbar_a), "r"(64u) : "memory");
    }
    __syncthreads();
    /* cluster-wide: mbarrier init + hbuf zero visible before any remote traffic */
    asm volatile("barrier.cluster.arrive.aligned;" ::: "memory");
    asm volatile("barrier.cluster.wait.aligned;"   ::: "memory");

    uint32_t hb_a0 = smem_u32(&hbuf[0][0]);
    uint32_t hb_a1 = smem_u32(&hbuf[1][0]);

    float cst = 0.f;
    float bconst = (zin == nullptr && half == 0) ? biasT[dir*1024 + grow] : 0.f;

    float zi = 0.f;
    if (half == 0){
        int time0 = dir ? (T-1) : 0;
        if (zin) zi = zin[(size_t)dir*T*8*1024 + ((size_t)time0*8+b)*1024 + grow];
        else {
            int v = idx[b*T + time0];
            zi = wihT[(size_t)dir*1024*44 + (size_t)grow*44 + v] + bconst;
        }
    }

    for (int t = 0; t < T; ++t){
        /* dot(h_half, w_half) from local smem hbuf[t&1] */
        const float* hrow = &hbuf[t&1][half*128];
        unsigned long long p0=0ull, p1=0ull, p2=0ull, p3=0ull;
        const ulonglong2* hv = (const ulonglong2*)hrow;
#pragma unroll
        for (int q=0;q<32;q+=2){
            ulonglong2 h0 = hv[q], h1 = hv[q+1];
            ulonglong2 w0 = *(const ulonglong2*)&rw[q];
            ulonglong2 w1 = *(const ulonglong2*)&rw[q+1];
            FMA2(p0, h0.x, w0.x); FMA2(p1, h0.y, w0.y);
            FMA2(p2, h1.x, w1.x); FMA2(p3, h1.y, w1.y);
        }
        float2 f0 = *(float2*)&p0, f1 = *(float2*)&p1;
        float2 f2 = *(float2*)&p2, f3 = *(float2*)&p3;
        float v = ((f0.x+f0.y)+(f1.x+f1.y)) + ((f2.x+f2.y)+(f3.x+f3.y)) + zi;
        v += __shfl_xor_sync(0xffffffffu, v, 1);

        /* prefetch next step's input term */
        float zn = 0.f;
        if (half == 0 && t+1 < T){
            int tn = dir ? (T-2-t) : (t+1);
            if (zin) zn = zin[(size_t)dir*T*8*1024 + ((size_t)tn*8+b)*1024 + grow];
            else {
                int vx = idx[b*T + tn];
                zn = wihT[(size_t)dir*1024*44 + (size_t)grow*44 + vx] + bconst;
            }
        }

        float gi = __shfl_sync(0xffffffffu, v, uu*2);
        float gf = __shfl_sync(0xffffffffu, v, 8  + uu*2);
        float gg = __shfl_sync(0xffffffffu, v, 16 + uu*2);
        float go = __shfl_sync(0xffffffffu, v, 24 + uu*2);

        float hval = 0.f;
        if (lane < 4){
            float c = sigf(gf)*cst + sigf(gi)*tanhfast(gg);
            cst = c;
            hval = sigf(go)*tanhfast(c);
            xbuf[w][t&63][uu] = hval;
        }
        /* broadcast the warp's 4 unit values to all lanes */
        float h0 = __shfl_sync(0xffffffffu, hval, 0);
        float h1 = __shfl_sync(0xffffffffu, hval, 1);
        float h2 = __shfl_sync(0xffffffffu, hval, 2);
        float h3 = __shfl_sync(0xffffffffu, hval, 3);

        /* lanes 0..7: store 16B slice to peer CTA 'lane', then arrive there */
        if (lane < 8){
            uint32_t dst = (((t+1)&1) ? hb_a1 : hb_a0) + (uint32_t)(ubase*4);
            uint32_t rdst, rbar;
            asm("mapa.shared::cluster.u32 %0, %1, %2;"
                : "=r"(rdst) : "r"(dst), "r"(lane));
            asm volatile("st.shared::cluster.v4.f32 [%0], {%1,%2,%3,%4};"
                         :: "r"(rdst), "f"(h0), "f"(h1), "f"(h2), "f"(h3)
                         : "memory");
            asm("mapa.shared::cluster.u32 %0, %1, %2;"
                : "=r"(rbar) : "r"(mbar_a), "r"(lane));
            asm volatile("mbarrier.arrive.release.cluster.shared::cluster.b64 _, [%0];"
                         :: "r"(rbar) : "memory");
        }
        zi = zn;

        /* wait for all 64 arrivals (phase parity = t&1), acquire at cluster scope */
        {
            uint32_t par = (uint32_t)(t & 1);
            uint32_t done;
            asm volatile(
                "{\n\t"
                ".reg .pred p;\n\t"
                "mbarrier.try_wait.parity.acquire.cluster.shared::cta.b64 p, [%1], %2;\n\t"
                "selp.b32 %0, 1, 0, p;\n\t"
                "}"
                : "=r"(done) : "r"(mbar_a), "r"(par) : "memory");
            if (!done){
                asm volatile(
                    "{\n\t"
                    ".reg .pred P1;\n\t"
                    "WL_%=:\n\t"
                    "mbarrier.try_wait.parity.acquire.cluster.shared::cta.b64 P1, [%0], %1, 0x989680;\n\t"
                    "@P1 bra.uni WD_%=;\n\t"
                    "bra.uni WL_%=;\n\t"
                    "WD_%=:\n\t"
                    "}"
                    :: "r"(mbar_a), "r"(par) : "memory");
            }
        }

        /* warp-private xout flush every 64 steps (T % 64 == 0) */
        if ((t & 63) == 63){
            int c0 = t - 63;
#pragma unroll
            for (int k=0;k<2;k++){
                int s_ = lane + k*32;
                int tt = c0 + s_;
                int time_ = dir ? (T-1-tt) : tt;
                float4 val = *(float4*)&xbuf[w][s_][0];
                size_t off;
                if (outMode == 0)
                    off = ((size_t)time_*8 + b)*512 + dir*256 + ubase;
                else
                    off = ((size_t)b*T + time_)*512 + dir*256 + ubase;
                *(float4*)&xout[off] = val;
            }
        }
    }

    /* no CTA may exit while peers could still address its smem */
    asm volatile("barrier.cluster.arrive.aligned;" ::: "memory");
    asm volatile("barrier.cluster.wait.aligned;"   ::: "memory");
}

/* ---------------- DTW (double-buffered, 1 sync/row) ---------------- */
__global__ void __launch_bounds__(512) k_dtw(float* __restrict__ out){
    int b = blockIdx.x, tid = threadIdx.x;
    __shared__ float bufA[520], bufB[520];
    if (tid == 0){ bufA[0] = FPOS; bufB[0] = FNEG; }
    bufA[tid+1] = FNEG;
    __syncthreads();
    const float* srow = g_scores + (size_t)b*NFR*LTXT;
    float* orow = out + (size_t)b*NFR*LTXT;
    float snext = srow[tid];
    for (int n=0; n<NFR; n++){
        float* src = (n & 1) ? bufB : bufA;
        float* dst = (n & 1) ? bufA : bufB;
        float s = snext;
        if (n+1 < NFR) snext = srow[(size_t)(n+1)*LTXT + tid];
        float v = s + fmaxf(src[tid+1], src[tid]);
        dst[tid+1] = v;
        if (n == 0 && tid == 0) bufA[0] = FNEG;
        orow[(size_t)n*LTXT + tid] = v;
        __syncthreads();
    }
}

/* ---------------- host launcher ---------------- */
static inline dim3 gemm_grid(int M, int N, int Z){
    return dim3((N+127)/128, (M+127)/128, Z);
}

extern "C" void kernel_launch(void* const* d_in, const int* in_sizes, int n_in,
                              void* d_out, int out_size)
{
    const float* x_audio  = (const float*)d_in[0];
    const int*   text_idx = (const int*)  d_in[1];
    const float* txt_wih  = (const float*)d_in[2];
    const float* txt_whh  = (const float*)d_in[3];
    const float* txt_b    = (const float*)d_in[4];
    const float* w_s      = (const float*)d_in[5];
    const float* fc1_w    = (const float*)d_in[6];
    const float* bn1_g    = (const float*)d_in[7];
    const float* bn1_b    = (const float*)d_in[8];
    const float* in_mean  = (const float*)d_in[9];
    const float* in_scale = (const float*)d_in[10];
    const float* ae_wih   = (const float*)d_in[11];
    const float* ae_whh   = (const float*)d_in[12];
    const float* ae_b     = (const float*)d_in[13];
    float* out = (float*)d_out;

    void *p_table, *p_frames, *p_stft, *p_feat, *p_fc1p, *p_prebn;
    void *p_x0, *p_x1, *p_x2, *p_zbuf, *p_htext, *p_side, *p_scores;
    cudaGetSymbolAddress(&p_table,  g_table);
    cudaGetSymbolAddress(&p_frames, g_frames);
    cudaGetSymbolAddress(&p_stft,   g_stft);
    cudaGetSymbolAddress(&p_feat,   g_feat);
    cudaGetSymbolAddress(&p_fc1p,   g_fc1p);
    cudaGetSymbolAddress(&p_prebn,  g_prebn);
    cudaGetSymbolAddress(&p_x0,     g_x0);
    cudaGetSymbolAddress(&p_x1,     g_x1);
    cudaGetSymbolAddress(&p_x2,     g_x2);
    cudaGetSymbolAddress(&p_zbuf,   g_zbuf);
    cudaGetSymbolAddress(&p_htext,  g_htext);
    cudaGetSymbolAddress(&p_side,   g_side);
    cudaGetSymbolAddress(&p_scores, g_scores);

    /* 1. table (zeroes BN stats), frames, weight pad */
    k_table<<<(STFTN*NFFT+255)/256, 256>>>();
    k_frames<<<(AROWS*NFFT+255)/256, 256>>>(x_audio);
    k_padw<<<(512*KPAD+255)/256, 256>>>(fc1_w);

    /* 2. text bi-LSTM — 4th launch so ncu (-s 5 -c 1) profiles it */
    k_lstm<<<128, 256>>>(nullptr, txt_whh, txt_wih, txt_b, text_idx,
                         (float*)p_htext, LTXT, 1);

    /* 3. STFT GEMM */
    k_gemm<<<gemm_grid(AROWS, STFTN, 1), 256>>>(
        (const float*)p_frames, NFFT, 0,
        (const float*)p_table,  NFFT, 0,
        (float*)p_stft, STFTN, 0,
        nullptr, 0, AROWS, STFTN, NFFT);

    /* 4. magnitude + input_mean/scale */
    k_magfeat<<<(AROWS*KPAD+255)/256, 256>>>(in_mean, in_scale);

    /* 5. fc1 */
    k_gemm<<<gemm_grid(AROWS, HIDD, 1), 256>>>(
        (const float*)p_feat, KPAD, 0,
        (const float*)p_fc1p, KPAD, 0,
        (float*)p_prebn, HIDD, 0,
        nullptr, 0, AROWS, HIDD, KPAD);

    /* 6. BatchNorm + tanh -> g_x0 */
    k_bnstats<<<128, 256>>>();
    k_bnapply<<<(int)(((size_t)AROWS*HIDD+255)/256), 256>>>(bn1_g, bn1_b);

    /* 7. audio LSTM layer 0 */
    k_gemm<<<gemm_grid(AROWS, 1024, 2), 256>>>(
        (const float*)p_x0, HIDD, 0,
        ae_wih + (size_t)0*2*1024*512, HIDD, (long long)1024*512,
        (float*)p_zbuf, 1024, (long long)AROWS*1024,
        ae_b + (size_t)0*2*1024, 1024,
        AROWS, 1024, HIDD);
    k_lstm<<<128, 256>>>((const float*)p_zbuf,
                         ae_whh + (size_t)0*2*1024*256,
                         nullptr, nullptr, nullptr,
                         (float*)p_x1, NFR, 0);

    /* 8. audio LSTM layer 1 */
    k_gemm<<<gemm_grid(AROWS, 1024, 2), 256>>>(
        (const float*)p_x1, HIDD, 0,
        ae_wih + (size_t)1*2*1024*512, HIDD, (long long)1024*512,
        (float*)p_zbuf, 1024, (long long)AROWS*1024,
        ae_b + (size_t)1*2*1024, 1024,
        AROWS, 1024, HIDD);
    k_lstm<<<128, 256>>>((const float*)p_zbuf,
                         ae_whh + (size_t)1*2*1024*256,
                         nullptr, nullptr, nullptr,
                         (float*)p_x2, NFR, 0);

    /* 9. side */
    k_gemm<<<gemm_grid(512, 512, BATCHB), 256>>>(
        (const float*)p_htext, 512, (long long)512*512,
        w_s, 512, 0,
        (float*)p_side, 512, (long long)512*512,
        nullptr, 0, 512, 512, 512);

    /* 10. scores */
    k_gemm<<<gemm_grid(NFR, LTXT, BATCHB), 256>>>(
        (const float*)p_x2, 8*512, 512,
        (const float*)p_side, 512, (long long)512*512,
        (float*)p_scores, LTXT, (long long)NFR*LTXT,
        nullptr, 0, NFR, LTXT, HIDD);

    /* 11. DTW */
    k_dtw<<<BATCHB, 512>>>(out);
}

// round 14
// speedup vs baseline: 1.4431x; 1.4431x over previous
#include <cuda_runtime.h>
#include <cuda_bf16.h>
#include <math.h>
#include <stdint.h>

#define NFR    2048
#define BATCHB 8
#define AROWS  (NFR*BATCHB)     /* 16384 */
#define NBINS  257
#define STFTN  514
#define NFFT   512
#define HIDD   512
#define TAUD   524544
#define LTXT   512
#define KPAD   272
#define FPOS   200000.0f
#define FNEG   (-100000.0f)
#define NCC    8                /* CTAs per (dir,batch) chain */

#define FMA2(d,a,b) asm("fma.rn.f32x2 %0, %1, %2, %0;" : "+l"(d) : "l"(a), "l"(b))

/* ---------------- static device scratch ---------------- */
__device__ float  g_table[STFTN*NFFT];
__device__ float  g_frames[(size_t)AROWS*NFFT];
__device__ float  g_stft[(size_t)AROWS*STFTN];
__device__ float  g_feat[(size_t)AROWS*KPAD];
__device__ float  g_fc1p[512*KPAD];
__device__ float  g_prebn[(size_t)AROWS*HIDD];
__device__ double g_bnstat[1024];
__device__ float  g_x0[(size_t)AROWS*HIDD];
__device__ float  g_x1[(size_t)AROWS*HIDD];
__device__ float  g_x2[(size_t)AROWS*HIDD];
__device__ float  g_zbuf[(size_t)2*AROWS*1024];
__device__ float  g_htext[(size_t)BATCHB*LTXT*HIDD];
__device__ float  g_side[(size_t)BATCHB*512*512];
__device__ float  g_scores[(size_t)BATCHB*NFR*LTXT];
__device__ float  g_lhex[16*2*256];   /* [chain][parity][k] ; 128B line per CTA */
__device__ int    g_ctr[3*16*32];     /* 3 launches x 16 chains, 128B apart */

static __device__ __forceinline__ float sigf(float x){
    return __fdividef(1.0f, 1.0f + __expf(-x));
}
static __device__ __forceinline__ float tanhfast(float x){
    return 1.0f - __fdividef(2.0f, __expf(2.0f*x) + 1.0f);
}

static __device__ __forceinline__ uint32_t f2tf(float x){
    uint32_t r; asm("cvt.rna.tf32.f32 %0, %1;" : "=r"(r) : "f"(x)); return r;
}
static __device__ __forceinline__ void mma8(float4& d,
    uint32_t a0,uint32_t a1,uint32_t a2,uint32_t a3,uint32_t b0,uint32_t b1){
    asm("mma.sync.aligned.m16n8k8.row.col.f32.tf32.tf32.f32 "
        "{%0,%1,%2,%3},{%4,%5,%6,%7},{%8,%9},{%0,%1,%2,%3};"
        : "+f"(d.x),"+f"(d.y),"+f"(d.z),"+f"(d.w)
        : "r"(a0),"r"(a1),"r"(a2),"r"(a3),"r"(b0),"r"(b1));
}

/* ---------------- init kernels ---------------- */
__global__ void k_table(){
    int i = blockIdx.x*blockDim.x + threadIdx.x;
    if (i < 3*16*32) g_ctr[i] = 0;         /* all LSTM barrier counters */
    if (i < 1024)    g_bnstat[i] = 0.0;    /* BN accumulators */
    if (i >= STFTN*NFFT) return;
    int j = i >> 9, k = i & 511;
    int bin = (j < NBINS) ? j : (j - NBINS);
    int ph = (k*bin) & 511;
    float ang = (float)ph * 0.012271846303085130f;
    g_table[i] = (j < NBINS) ? cosf(ang) : sinf(ang);
}

__global__ void k_frames(const float* __restrict__ x){
    int i = blockIdx.x*blockDim.x + threadIdx.x;
    if (i >= AROWS*NFFT) return;
    int row = i >> 9, n = i & 511;
    int f = row >> 3, b = row & 7;
    float w = 0.5f*(1.0f - cosf((float)n * 0.012271846303085130f));
    g_frames[i] = x[(size_t)b*TAUD + f*256 + n] * w;
}

__global__ void k_magfeat(const float* __restrict__ mean, const float* __restrict__ scale){
    int i = blockIdx.x*blockDim.x + threadIdx.x;
    if (i >= AROWS*KPAD) return;
    int row = i / KPAD, col = i - row*KPAD;
    float v = 0.f;
    if (col < NBINS){
        float re = g_stft[(size_t)row*STFTN + col];
        float im = g_stft[(size_t)row*STFTN + NBINS + col];
        v = (sqrtf(re*re + im*im) + mean[col]) * scale[col];
    }
    g_feat[i] = v;
}

__global__ void k_padw(const float* __restrict__ w){
    int i = blockIdx.x*blockDim.x + threadIdx.x;
    if (i >= 512*KPAD) return;
    int r = i / KPAD, c = i - r*KPAD;
    g_fc1p[i] = (c < NBINS) ? w[r*NBINS + c] : 0.f;
}

/* ---------------- tf32 tensor-core GEMM (unchanged) ---------------- */
__global__ void __launch_bounds__(256) k_gemm(
    const float* __restrict__ A, int lda, long long sA,
    const float* __restrict__ B, int ldb, long long sB,
    float* __restrict__ C, int ldc, long long sC,
    const float* __restrict__ bias, long long sBias,
    int M, int N, int K)
{
    __shared__ uint32_t As[2][128*16];
    __shared__ uint32_t Bs[2][128*16];
    int tid = threadIdx.x;
    int bz = blockIdx.z;
    A += (size_t)bz*sA; B += (size_t)bz*sB; C += (size_t)bz*sC;
    int m0 = blockIdx.y*128, n0 = blockIdx.x*128;

    int wid = tid >> 5, lane = tid & 31;
    int wm = wid & 3, wn = wid >> 2;
    int g = lane >> 2, tg = lane & 3;
    int aoff = ((tg ^ (g & 3)) << 2);

    int lrow = tid >> 2, lkq = tid & 3;

    float4 acc[2][8];
#pragma unroll
    for (int i=0;i<2;i++)
#pragma unroll
        for (int j=0;j<8;j++) acc[i][j] = make_float4(0.f,0.f,0.f,0.f);

    const float4 z4 = make_float4(0.f,0.f,0.f,0.f);
    int mm0 = m0 + lrow, mm1 = m0 + lrow + 64;
    int nn0 = n0 + lrow, nn1 = n0 + lrow + 64;

    float4 pA0, pA1, pB0, pB1;
    pA0 = (mm0 < M) ? *(const float4*)(A + (size_t)mm0*lda + lkq*4) : z4;
    pA1 = (mm1 < M) ? *(const float4*)(A + (size_t)mm1*lda + lkq*4) : z4;
    pB0 = (nn0 < N) ? *(const float4*)(B + (size_t)nn0*ldb + lkq*4) : z4;
    pB1 = (nn1 < N) ? *(const float4*)(B + (size_t)nn1*ldb + lkq*4) : z4;

    int s0 = lrow & 3;
    {
        uint32_t* b0 = As[0] + lrow*16 + lkq;
        b0[((0^s0)<<2)] = f2tf(pA0.x); b0[((1^s0)<<2)] = f2tf(pA0.y);
        b0[((2^s0)<<2)] = f2tf(pA0.z); b0[((3^s0)<<2)] = f2tf(pA0.w);
        uint32_t* b1 = As[0] + (lrow+64)*16 + lkq;
        b1[((0^s0)<<2)] = f2tf(pA1.x); b1[((1^s0)<<2)] = f2tf(pA1.y);
        b1[((2^s0)<<2)] = f2tf(pA1.z); b1[((3^s0)<<2)] = f2tf(pA1.w);
        uint32_t* c0 = Bs[0] + lrow*16 + lkq;
        c0[((0^s0)<<2)] = f2tf(pB0.x); c0[((1^s0)<<2)] = f2tf(pB0.y);
        c0[((2^s0)<<2)] = f2tf(pB0.z); c0[((3^s0)<<2)] = f2tf(pB0.w);
        uint32_t* c1 = Bs[0] + (lrow+64)*16 + lkq;
        c1[((0^s0)<<2)] = f2tf(pB1.x); c1[((1^s0)<<2)] = f2tf(pB1.y);
        c1[((2^s0)<<2)] = f2tf(pB1.z); c1[((3^s0)<<2)] = f2tf(pB1.w);
    }
    __syncthreads();

    int kt = K >> 4;
    for (int kb = 0; kb < kt; kb++){
        int buf = kb & 1;
        bool more = (kb + 1 < kt);
        if (more){
            int ko = (kb+1)*16;
            pA0 = (mm0 < M) ? *(const float4*)(A + (size_t)mm0*lda + ko + lkq*4) : z4;
            pA1 = (mm1 < M) ? *(const float4*)(A + (size_t)mm1*lda + ko + lkq*4) : z4;
            pB0 = (nn0 < N) ? *(const float4*)(B + (size_t)nn0*ldb + ko + lkq*4) : z4;
            pB1 = (nn1 < N) ? *(const float4*)(B + (size_t)nn1*ldb + ko + lkq*4) : z4;
        }

        uint4 aLo[2], aHi[2];
#pragma unroll
        for (int i=0;i<2;i++){
            int r = wm*32 + i*16 + g;
            aLo[i] = *(const uint4*)&As[buf][r*16 + aoff];
            aHi[i] = *(const uint4*)&As[buf][(r+8)*16 + aoff];
        }
#pragma unroll
        for (int j=0;j<8;j++){
            uint4 bv = *(const uint4*)&Bs[buf][(wn*64 + j*8 + g)*16 + aoff];
#pragma unroll
            for (int i=0;i<2;i++){
                mma8(acc[i][j], aLo[i].x, aHi[i].x, aLo[i].y, aHi[i].y, bv.x, bv.y);
                mma8(acc[i][j], aLo[i].z, aHi[i].z, aLo[i].w, aHi[i].w, bv.z, bv.w);
            }
        }

        if (more){
            int nb = buf ^ 1;
            uint32_t* b0 = As[nb] + lrow*16 + lkq;
            b0[((0^s0)<<2)] = f2tf(pA0.x); b0[((1^s0)<<2)] = f2tf(pA0.y);
            b0[((2^s0)<<2)] = f2tf(pA0.z); b0[((3^s0)<<2)] = f2tf(pA0.w);
            uint32_t* b1 = As[nb] + (lrow+64)*16 + lkq;
            b1[((0^s0)<<2)] = f2tf(pA1.x); b1[((1^s0)<<2)] = f2tf(pA1.y);
            b1[((2^s0)<<2)] = f2tf(pA1.z); b1[((3^s0)<<2)] = f2tf(pA1.w);
            uint32_t* c0 = Bs[nb] + lrow*16 + lkq;
            c0[((0^s0)<<2)] = f2tf(pB0.x); c0[((1^s0)<<2)] = f2tf(pB0.y);
            c0[((2^s0)<<2)] = f2tf(pB0.z); c0[((3^s0)<<2)] = f2tf(pB0.w);
            uint32_t* c1 = Bs[nb] + (lrow+64)*16 + lkq;
            c1[((0^s0)<<2)] = f2tf(pB1.x); c1[((1^s0)<<2)] = f2tf(pB1.y);
            c1[((2^s0)<<2)] = f2tf(pB1.z); c1[((3^s0)<<2)] = f2tf(pB1.w);
        }
        __syncthreads();
    }

#pragma unroll
    for (int i=0;i<2;i++){
        int r0 = m0 + wm*32 + i*16 + g;
#pragma unroll
        for (int j=0;j<8;j++){
            int col = n0 + wn*64 + j*8 + tg*2;
            if (col + 2 <= N){
                float bx = bias ? bias[(size_t)bz*sBias + col]     : 0.f;
                float by = bias ? bias[(size_t)bz*sBias + col + 1] : 0.f;
                if (r0 < M)
                    *(float2*)&C[(size_t)r0*ldc + col] =
                        make_float2(acc[i][j].x + bx, acc[i][j].y + by);
                if (r0 + 8 < M)
                    *(float2*)&C[(size_t)(r0+8)*ldc + col] =
                        make_float2(acc[i][j].z + bx, acc[i][j].w + by);
            } else if (col < N){
                float bx = bias ? bias[(size_t)bz*sBias + col] : 0.f;
                if (r0 < M)     C[(size_t)r0*ldc + col]     = acc[i][j].x + bx;
                if (r0 + 8 < M) C[(size_t)(r0+8)*ldc + col] = acc[i][j].z + bx;
            }
        }
    }
}

/* ---------------- BatchNorm (stats zeroed in k_table) ---------------- */
__global__ void k_bnstats(){
    int r0 = blockIdx.x * 128;
    int c = threadIdx.x;
    double s0=0,q0=0,s1=0,q1=0;
    for (int r=0;r<128;r++){
        float v0 = g_prebn[(size_t)(r0+r)*512 + c];
        float v1 = g_prebn[(size_t)(r0+r)*512 + c + 256];
        s0 += v0; q0 += (double)v0*v0;
        s1 += v1; q1 += (double)v1*v1;
    }
    atomicAdd(&g_bnstat[c], s0);       atomicAdd(&g_bnstat[512+c], q0);
    atomicAdd(&g_bnstat[c+256], s1);   atomicAdd(&g_bnstat[512+c+256], q1);
}

__global__ void k_bnapply(const float* __restrict__ gam, const float* __restrict__ bet){
    size_t i = (size_t)blockIdx.x*blockDim.x + threadIdx.x;
    if (i >= (size_t)AROWS*512) return;
    int col = (int)(i & 511);
    double mu = g_bnstat[col] * (1.0/16384.0);
    double var = g_bnstat[512+col] * (1.0/16384.0) - mu*mu;
    float rs = rsqrtf((float)var + 1e-5f);
    float v = g_prebn[i];
    g_x0[i] = tanhf(gam[col]*(v-(float)mu)*rs + bet[col]);
}

/* ---------------- persistent bi-LSTM: per-chain, per-warp poll ----------------
   128 CTAs = 16 (dir,batch) chains x 8 CTAs. CTA owns 32 hidden units (one
   contiguous 128B hex line). Per-chain counter, 8 arrivals. bar1 + tid0
   red.release order the CTA's hex stores; the WAIT is per-warp (all lanes
   ld.acquire the same counter) so there is no second CTA barrier.            */
__global__ void __launch_bounds__(256,1) k_lstm(
    const float* __restrict__ zin,    /* [dir][T*8][1024] or null (text) */
    const float* __restrict__ whh,    /* [dir][1024][256] */
    const float* __restrict__ wihT,   /* text: [dir][1024][44] */
    const float* __restrict__ biasT,  /* text: [dir][1024] */
    const int*   __restrict__ idx,    /* text: [8][T] */
    float* __restrict__ xout,
    int* __restrict__ ctrbase,
    int T, int outMode)
{
    int cta   = blockIdx.x;
    int chain = cta >> 3;          /* 0..15 = dir*8 + b */
    int cid   = cta & 7;
    int dir   = chain >> 3;
    int b     = chain & 7;
    int tid   = threadIdx.x;
    int w     = tid >> 5;
    int lane  = tid & 31;
    int r = lane >> 1, half = lane & 1;
    int g = r >> 2, u = r & 3;
    int ubase = cid*32 + w*4;      /* this warp's 4 units */
    int grow  = g*256 + ubase + u;
    int uu = lane & 3;

    __shared__ float h_s[8*256];           /* per-warp private h copies */
    __shared__ float xbuf[8][64][4];       /* [warp][step&63][unit] */

    float4 rw[32];
    {
        const float4* wsrc = (const float4*)(whh + (size_t)dir*1024*256
                                             + (size_t)grow*256 + half*128);
#pragma unroll
        for (int q=0;q<32;q++) rw[q] = wsrc[q];
    }
    float* h_w = h_s + w*256;
    ((float4*)h_w)[lane]      = make_float4(0.f,0.f,0.f,0.f);
    ((float4*)h_w)[lane + 32] = make_float4(0.f,0.f,0.f,0.f);
    __syncthreads();

    float cst = 0.f;
    float* hex = g_lhex + chain*512;       /* [parity][256] */
    int* ctr = ctrbase + chain*32;
    const float* hrow = h_w + half*128;
    float bconst = (zin == nullptr && half == 0) ? biasT[dir*1024 + grow] : 0.f;

    float zi = 0.f;
    if (half == 0){
        int time0 = dir ? (T-1) : 0;
        if (zin) zi = zin[(size_t)dir*T*8*1024 + ((size_t)time0*8+b)*1024 + grow];
        else {
            int v = idx[b*T + time0];
            zi = wihT[(size_t)dir*1024*44 + (size_t)grow*44 + v] + bconst;
        }
    }

    for (int t = 0; t < T; ++t){
        /* dot(h_half, w_half) in f32x2 */
        unsigned long long p0=0ull, p1=0ull, p2=0ull, p3=0ull;
        const ulonglong2* hv = (const ulonglong2*)hrow;
#pragma unroll
        for (int q=0;q<32;q+=2){
            ulonglong2 h0 = hv[q], h1 = hv[q+1];
            ulonglong2 w0 = *(const ulonglong2*)&rw[q];
            ulonglong2 w1 = *(const ulonglong2*)&rw[q+1];
            FMA2(p0, h0.x, w0.x); FMA2(p1, h0.y, w0.y);
            FMA2(p2, h1.x, w1.x); FMA2(p3, h1.y, w1.y);
        }
        float2 f0 = *(float2*)&p0, f1 = *(float2*)&p1;
        float2 f2 = *(float2*)&p2, f3 = *(float2*)&p3;
        float v = ((f0.x+f0.y)+(f1.x+f1.y)) + ((f2.x+f2.y)+(f3.x+f3.y)) + zi;
        v += __shfl_xor_sync(0xffffffffu, v, 1);

        /* prefetch next step's input term */
        float zn = 0.f;
        if (half == 0 && t+1 < T){
            int tn = dir ? (T-2-t) : (t+1);
            if (zin) zn = zin[(size_t)dir*T*8*1024 + ((size_t)tn*8+b)*1024 + grow];
            else {
                int vx = idx[b*T + tn];
                zn = wihT[(size_t)dir*1024*44 + (size_t)grow*44 + vx] + bconst;
            }
        }

        float gi = __shfl_sync(0xffffffffu, v, uu*2);
        float gf = __shfl_sync(0xffffffffu, v, 8  + uu*2);
        float gg = __shfl_sync(0xffffffffu, v, 16 + uu*2);
        float go = __shfl_sync(0xffffffffu, v, 24 + uu*2);

        if (lane < 4){
            float c = sigf(gf)*cst + sigf(gi)*tanhfast(gg);
            cst = c;
            float hval = sigf(go)*tanhfast(c);
            __stcg(&hex[(t&1)*256 + ubase + uu], hval);
            xbuf[w][t&63][uu] = hval;
        }
        zi = zn;

        __syncthreads();                 /* CTA's 128B hex line complete before release */
        if (tid == 0){
            asm volatile("red.release.gpu.global.add.s32 [%0], 1;"
                         :: "l"(ctr) : "memory");
        }
        /* per-warp wait: all lanes acquire-poll the same counter (1 req/iter) */
        {
            int tgt = NCC*(t+1), cv;
            do {
                asm volatile("ld.acquire.gpu.global.s32 %0, [%1];"
                             : "=r"(cv) : "l"(ctr) : "memory");
            } while (cv < tgt);
        }

        /* warp reloads the chain's 256-float h into its private copy */
        {
            const float4* src = (const float4*)(hex + (t&1)*256);
            float4 v0 = __ldcg(src + lane);
            float4 v1 = __ldcg(src + lane + 32);
            ((float4*)h_w)[lane]      = v0;
            ((float4*)h_w)[lane + 32] = v1;
        }
        __syncwarp();

        /* warp-private xout flush every 64 steps (T % 64 == 0) */
        if ((t & 63) == 63){
            int c0 = t - 63;
#pragma unroll
            for (int k=0;k<2;k++){
                int s_ = lane + k*32;
                int tt = c0 + s_;
                int time_ = dir ? (T-1-tt) : tt;
                float4 val = *(float4*)&xbuf[w][s_][0];
                size_t off;
                if (outMode == 0)
                    off = ((size_t)time_*8 + b)*512 + dir*256 + ubase;
                else
                    off = ((size_t)b*T + time_)*512 + dir*256 + ubase;
                *(float4*)&xout[off] = val;
            }
        }
    }
}

/* ---------------- DTW (double-buffered, 1 sync/row) ---------------- */
__global__ void __launch_bounds__(512) k_dtw(float* __restrict__ out){
    int b = blockIdx.x, tid = threadIdx.x;
    __shared__ float bufA[520], bufB[520];
    if (tid == 0){ bufA[0] = FPOS; bufB[0] = FNEG; }
    bufA[tid+1] = FNEG;
    __syncthreads();
    const float* srow = g_scores + (size_t)b*NFR*LTXT;
    float* orow = out + (size_t)b*NFR*LTXT;
    float snext = srow[tid];
    for (int n=0; n<NFR; n++){
        float* src = (n & 1) ? bufB : bufA;
        float* dst = (n & 1) ? bufA : bufB;
        float s = snext;
        if (n+1 < NFR) snext = srow[(size_t)(n+1)*LTXT + tid];
        float v = s + fmaxf(src[tid+1], src[tid]);
        dst[tid+1] = v;
        if (n == 0 && tid == 0) bufA[0] = FNEG;
        orow[(size_t)n*LTXT + tid] = v;
        __syncthreads();
    }
}

/* ---------------- host launcher ---------------- */
static inline dim3 gemm_grid(int M, int N, int Z){
    return dim3((N+127)/128, (M+127)/128, Z);
}

extern "C" void kernel_launch(void* const* d_in, const int* in_sizes, int n_in,
                              void* d_out, int out_size)
{
    const float* x_audio  = (const float*)d_in[0];
    const int*   text_idx = (const int*)  d_in[1];
    const float* txt_wih  = (const float*)d_in[2];
    const float* txt_whh  = (const float*)d_in[3];
    const float* txt_b    = (const float*)d_in[4];
    const float* w_s      = (const float*)d_in[5];
    const float* fc1_w    = (const float*)d_in[6];
    const float* bn1_g    = (const float*)d_in[7];
    const float* bn1_b    = (const float*)d_in[8];
    const float* in_mean  = (const float*)d_in[9];
    const float* in_scale = (const float*)d_in[10];
    const float* ae_wih   = (const float*)d_in[11];
    const float* ae_whh   = (const float*)d_in[12];
    const float* ae_b     = (const float*)d_in[13];
    float* out = (float*)d_out;

    void *p_table, *p_frames, *p_stft, *p_feat, *p_fc1p, *p_prebn;
    void *p_x0, *p_x1, *p_x2, *p_zbuf, *p_htext, *p_side, *p_scores, *p_ctr;
    cudaGetSymbolAddress(&p_table,  g_table);
    cudaGetSymbolAddress(&p_frames, g_frames);
    cudaGetSymbolAddress(&p_stft,   g_stft);
    cudaGetSymbolAddress(&p_feat,   g_feat);
    cudaGetSymbolAddress(&p_fc1p,   g_fc1p);
    cudaGetSymbolAddress(&p_prebn,  g_prebn);
    cudaGetSymbolAddress(&p_x0,     g_x0);
    cudaGetSymbolAddress(&p_x1,     g_x1);
    cudaGetSymbolAddress(&p_x2,     g_x2);
    cudaGetSymbolAddress(&p_zbuf,   g_zbuf);
    cudaGetSymbolAddress(&p_htext,  g_htext);
    cudaGetSymbolAddress(&p_side,   g_side);
    cudaGetSymbolAddress(&p_scores, g_scores);
    cudaGetSymbolAddress(&p_ctr,    g_ctr);
    int* ctr0 = (int*)p_ctr;              /* audio layer 0: 16*32 ints */
    int* ctr1 = (int*)p_ctr + 16*32;      /* audio layer 1 */
    int* ctr2 = (int*)p_ctr + 32*32;      /* text          */

    /* 1. table (zeroes counters + BN stats), frames, weight pad */
    k_table<<<(STFTN*NFFT+255)/256, 256>>>();
    k_frames<<<(AROWS*NFFT+255)/256, 256>>>(x_audio);
    k_padw<<<(512*KPAD+255)/256, 256>>>(fc1_w);

    /* 2. text bi-LSTM */
    k_lstm<<<128, 256>>>(nullptr, txt_whh, txt_wih, txt_b, text_idx,
                         (float*)p_htext, ctr2, LTXT, 1);

    /* 3. STFT GEMM */
    k_gemm<<<gemm_grid(AROWS, STFTN, 1), 256>>>(
        (const float*)p_frames, NFFT, 0,
        (const float*)p_table,  NFFT, 0,
        (float*)p_stft, STFTN, 0,
        nullptr, 0, AROWS, STFTN, NFFT);

    /* 4. magnitude + input_mean/scale */
    k_magfeat<<<(AROWS*KPAD+255)/256, 256>>>(in_mean, in_scale);

    /* 5. fc1 */
    k_gemm<<<gemm_grid(AROWS, HIDD, 1), 256>>>(
        (const float*)p_feat, KPAD, 0,
        (const float*)p_fc1p, KPAD, 0,
        (float*)p_prebn, HIDD, 0,
        nullptr, 0, AROWS, HIDD, KPAD);

    /* 6. BatchNorm + tanh -> g_x0 */
    k_bnstats<<<128, 256>>>();
    k_bnapply<<<(int)(((size_t)AROWS*HIDD+255)/256), 256>>>(bn1_g, bn1_b);

    /* 7. audio LSTM layer 0 */
    k_gemm<<<gemm_grid(AROWS, 1024, 2), 256>>>(
        (const float*)p_x0, HIDD, 0,
        ae_wih + (size_t)0*2*1024*512, HIDD, (long long)1024*512,
        (float*)p_zbuf, 1024, (long long)AROWS*1024,
        ae_b + (size_t)0*2*1024, 1024,
        AROWS, 1024, HIDD);
    k_lstm<<<128, 256>>>((const float*)p_zbuf,
                         ae_whh + (size_t)0*2*1024*256,
                         nullptr, nullptr, nullptr,
                         (float*)p_x1, ctr0, NFR, 0);

    /* 8. audio LSTM layer 1 */
    k_gemm<<<gemm_grid(AROWS, 1024, 2), 256>>>(
        (const float*)p_x1, HIDD, 0,
        ae_wih + (size_t)1*2*1024*512, HIDD, (long long)1024*512,
        (float*)p_zbuf, 1024, (long long)AROWS*1024,
        ae_b + (size_t)1*2*1024, 1024,
        AROWS, 1024, HIDD);
    k_lstm<<<128, 256>>>((const float*)p_zbuf,
                         ae_whh + (size_t)1*2*1024*256,
                         nullptr, nullptr, nullptr,
                         (float*)p_x2, ctr1, NFR, 0);

    /* 9. side */
    k_gemm<<<gemm_grid(512, 512, BATCHB), 256>>>(
        (const float*)p_htext, 512, (long long)512*512,
        w_s, 512, 0,
        (float*)p_side, 512, (long long)512*512,
        nullptr, 0, 512, 512, 512);

    /* 10. scores */
    k_gemm<<<gemm_grid(NFR, LTXT, BATCHB), 256>>>(
        (const float*)p_x2, 8*512, 512,
        (const float*)p_side, 512, (long long)512*512,
        (float*)p_scores, LTXT, (long long)NFR*LTXT,
        nullptr, 0, NFR, LTXT, HIDD);

    /* 11. DTW */
    k_dtw<<<BATCHB, 512>>>(out);
}